// round 3
// baseline (speedup 1.0000x reference)
#include <cuda_runtime.h>
#include <cuda_bf16.h>
#include <math.h>

#define DNUM 256
#define GNUM 4096
#define CH   512
#define NEG_BIG (-1e30f)

// Device-global scratch (no allocations allowed)
__device__ int g_seg_start[GNUM + 1];
__device__ int g_is64;

// ---------------------------------------------------------------------------
// Detect whether batch is int64 or int32. int64 little-endian with values
// < 4096 gives (value, 0) 32-bit word pairs; sorted int32 mid-array values
// (~2048) are nonzero everywhere. Deterministic for the fixed input.
// ---------------------------------------------------------------------------
__global__ void detect_kernel(const void* __restrict__ batch, int n) {
    const int* p = (const int*)batch;
    long base = ((long)(n / 2)) & ~1L;   // even word index, safely in-bounds for int32 view
    int hits = 0;
    for (int k = 0; k < 16; k += 2) {
        if (p[base + k + 1] == 0 && p[base + k] != 0) hits++;
    }
    g_is64 = (hits >= 6) ? 1 : 0;
}

__device__ __forceinline__ long long load_batch(const void* b, int i, int is64) {
    return is64 ? ((const long long*)b)[i] : (long long)((const int*)b)[i];
}

// ---------------------------------------------------------------------------
// Segment offsets via binary search (batch is sorted).
// seg_start[g] = first index i with batch[i] >= g ; seg_start[G] = n.
// ---------------------------------------------------------------------------
__global__ void seg_offsets_kernel(const void* __restrict__ batch, int n) {
    int t = blockIdx.x * blockDim.x + threadIdx.x;
    if (t > GNUM) return;
    if (t == GNUM) { g_seg_start[GNUM] = n; return; }
    int is64 = g_is64;
    int lo = 0, hi = n;
    while (lo < hi) {
        int mid = (lo + hi) >> 1;
        long long v = load_batch(batch, mid, is64);
        if (v < (long long)t) lo = mid + 1; else hi = mid;
    }
    g_seg_start[t] = lo;
}

// ---------------------------------------------------------------------------
// One block per segment. 256 threads: thread t owns output column t.
// Chunked online-softmax so arbitrarily long segments are handled.
// ---------------------------------------------------------------------------
__global__ __launch_bounds__(256)
void pool_kernel(const float* __restrict__ x,
                 const float* __restrict__ Wg,
                 const float* __restrict__ bg,
                 float* __restrict__ out) {
    __shared__ float sg[CH];
    __shared__ float sred[8];
    __shared__ float s_mc;

    const int g    = blockIdx.x;
    const int s    = g_seg_start[g];
    const int e    = g_seg_start[g + 1];
    const int tid  = threadIdx.x;
    const int lane = tid & 31;
    const int wid  = tid >> 5;

    // Hoist Wg into registers (each lane holds 8 strided values)
    float wreg[8];
    #pragma unroll
    for (int j = 0; j < 8; j++) wreg[j] = Wg[lane + 32 * j];
    const float b0 = bg[0];

    float acc   = 0.0f;
    float m_run = NEG_BIG;
    float d_run = 0.0f;

    for (int c0 = s; c0 < e; c0 += CH) {
        const int cl = min(CH, e - c0);

        // --- gate pass: one warp per row, 8 warps round-robin over rows ---
        for (int r = wid; r < cl; r += 8) {
            const float* xr = x + (size_t)(c0 + r) * DNUM;
            float sum = 0.0f;
            #pragma unroll
            for (int j = 0; j < 8; j++) sum = fmaf(xr[lane + 32 * j], wreg[j], sum);
            #pragma unroll
            for (int o = 16; o > 0; o >>= 1)
                sum += __shfl_down_sync(0xFFFFFFFFu, sum, o);
            if (lane == 0) sg[r] = sum + b0;
        }
        __syncthreads();

        // --- chunk max (block reduce) ---
        float lm = NEG_BIG;
        for (int r = tid; r < cl; r += 256) lm = fmaxf(lm, sg[r]);
        #pragma unroll
        for (int o = 16; o > 0; o >>= 1)
            lm = fmaxf(lm, __shfl_down_sync(0xFFFFFFFFu, lm, o));
        if (lane == 0) sred[wid] = lm;
        __syncthreads();
        if (tid == 0) {
            float mc = sred[0];
            #pragma unroll
            for (int w = 1; w < 8; w++) mc = fmaxf(mc, sred[w]);
            s_mc = mc;
        }
        __syncthreads();
        const float m_c   = s_mc;
        const float m_new = fmaxf(m_run, m_c);

        // online rescale of running state
        const float scale = __expf(m_run - m_new);   // 0 on first chunk
        acc   *= scale;
        d_run *= scale;

        // exponentiate gates in smem
        for (int r = tid; r < cl; r += 256) sg[r] = __expf(sg[r] - m_new);
        __syncthreads();

        // --- weight pass: thread t accumulates column t ---
        const float* xp = x + (size_t)c0 * DNUM + tid;
        int r = 0;
        #pragma unroll 4
        for (; r + 4 <= cl; r += 4) {
            float w0 = sg[r + 0], w1 = sg[r + 1], w2 = sg[r + 2], w3 = sg[r + 3];
            float v0 = xp[(size_t)(r + 0) * DNUM];
            float v1 = xp[(size_t)(r + 1) * DNUM];
            float v2 = xp[(size_t)(r + 2) * DNUM];
            float v3 = xp[(size_t)(r + 3) * DNUM];
            d_run += w0 + w1 + w2 + w3;
            acc = fmaf(w0, v0, acc);
            acc = fmaf(w1, v1, acc);
            acc = fmaf(w2, v2, acc);
            acc = fmaf(w3, v3, acc);
        }
        for (; r < cl; r++) {
            float w = sg[r];
            d_run += w;
            acc = fmaf(w, xp[(size_t)r * DNUM], acc);
        }

        m_run = m_new;
        __syncthreads();   // protect sg before next chunk overwrites
    }

    out[(size_t)g * DNUM + tid] = (e > s) ? (acc / d_run) : 0.0f;
}

// ---------------------------------------------------------------------------
extern "C" void kernel_launch(void* const* d_in, const int* in_sizes, int n_in,
                              void* d_out, int out_size) {
    const float* x     = (const float*)d_in[0];
    const void*  batch = d_in[1];
    const float* Wg    = (const float*)d_in[2];
    const float* bg    = (const float*)d_in[3];
    float*       out   = (float*)d_out;
    const int n = in_sizes[1];   // N elements in batch

    detect_kernel<<<1, 1>>>(batch, n);
    seg_offsets_kernel<<<(GNUM + 1 + 255) / 256, 256>>>(batch, n);
    pool_kernel<<<GNUM, 256>>>(x, Wg, bg, out);
}

// round 4
// speedup vs baseline: 1.8272x; 1.8272x over previous
#include <cuda_runtime.h>
#include <cuda_bf16.h>
#include <math.h>

#define DNUM 256
#define GNUM 4096
#define TR   32          // tile rows staged in smem (32 KB)
#define NEG_BIG (-1e30f)

// Device-global scratch (no allocations allowed)
__device__ int g_seg_start[GNUM + 1];
__device__ int g_is64;

// ---------------------------------------------------------------------------
// Detect whether batch is int64 or int32 (values < 4096: int64 LE gives
// (value, 0) word pairs mid-array). Deterministic for the fixed input.
// ---------------------------------------------------------------------------
__global__ void detect_kernel(const void* __restrict__ batch, int n) {
    const int* p = (const int*)batch;
    long base = ((long)(n / 2)) & ~1L;
    int hits = 0;
    for (int k = 0; k < 16; k += 2) {
        if (p[base + k + 1] == 0 && p[base + k] != 0) hits++;
    }
    g_is64 = (hits >= 6) ? 1 : 0;
}

__device__ __forceinline__ long long load_batch(const void* b, int i, int is64) {
    return is64 ? ((const long long*)b)[i] : (long long)((const int*)b)[i];
}

// ---------------------------------------------------------------------------
// Segment offsets via binary search over the sorted batch array.
// ---------------------------------------------------------------------------
__global__ void seg_offsets_kernel(const void* __restrict__ batch, int n) {
    int t = blockIdx.x * blockDim.x + threadIdx.x;
    if (t > GNUM) return;
    if (t == GNUM) { g_seg_start[GNUM] = n; return; }
    int is64 = g_is64;
    int lo = 0, hi = n;
    while (lo < hi) {
        int mid = (lo + hi) >> 1;
        long long v = load_batch(batch, mid, is64);
        if (v < (long long)t) lo = mid + 1; else hi = mid;
    }
    g_seg_start[t] = lo;
}

// ---------------------------------------------------------------------------
// One block per segment, 256 threads (thread t owns output column t).
// SINGLE-READ design: stage TR rows of x in smem, compute gates from smem,
// online-softmax update, weight pass from smem. x crosses DRAM exactly once.
// ---------------------------------------------------------------------------
__global__ __launch_bounds__(256)
void pool_kernel(const float* __restrict__ x,
                 const float* __restrict__ Wg,
                 const float* __restrict__ bg,
                 float* __restrict__ out) {
    __shared__ float sx[TR * DNUM];   // 32 KB tile of x
    __shared__ float sg[TR];          // gates for the tile
    __shared__ float s_mc;

    const int g    = blockIdx.x;
    const int s    = g_seg_start[g];
    const int e    = g_seg_start[g + 1];
    const int tid  = threadIdx.x;
    const int lane = tid & 31;
    const int wid  = tid >> 5;

    // Wg hoisted into registers (each lane holds 8 strided values)
    float wreg[8];
    #pragma unroll
    for (int j = 0; j < 8; j++) wreg[j] = Wg[lane + 32 * j];
    const float b0 = bg[0];

    float acc   = 0.0f;
    float m_run = NEG_BIG;
    float d_run = 0.0f;

    const float4* __restrict__ x4 = (const float4*)x;

    for (int c0 = s; c0 < e; c0 += TR) {
        const int cl = min(TR, e - c0);

        // --- stage tile: coalesced float4 loads, x read ONCE from DRAM ---
        {
            float4* sx4 = (float4*)sx;
            const float4* src = x4 + (size_t)c0 * (DNUM / 4);
            const int nw = cl * (DNUM / 4);          // float4 words in tile
            #pragma unroll 2
            for (int i = tid; i < nw; i += 256) sx4[i] = src[i];
        }
        __syncthreads();

        // --- gate pass from smem: one warp per row ---
        for (int r = wid; r < cl; r += 8) {
            const float* xr = sx + r * DNUM;
            float sum = 0.0f;
            #pragma unroll
            for (int j = 0; j < 8; j++) sum = fmaf(xr[lane + 32 * j], wreg[j], sum);
            #pragma unroll
            for (int o = 16; o > 0; o >>= 1)
                sum += __shfl_down_sync(0xFFFFFFFFu, sum, o);
            if (lane == 0) sg[r] = sum + b0;
        }
        __syncthreads();

        // --- tile max: warp 0 reduces the (<=32) gates ---
        if (wid == 0) {
            float lm = (lane < cl) ? sg[lane] : NEG_BIG;
            #pragma unroll
            for (int o = 16; o > 0; o >>= 1)
                lm = fmaxf(lm, __shfl_down_sync(0xFFFFFFFFu, lm, o));
            if (lane == 0) s_mc = lm;
        }
        __syncthreads();
        const float m_new = fmaxf(m_run, s_mc);

        // online rescale of running state
        const float scale = __expf(m_run - m_new);   // 0 on first tile
        acc   *= scale;
        d_run *= scale;

        // exponentiate gates
        if (tid < cl) sg[tid] = __expf(sg[tid] - m_new);
        __syncthreads();

        // --- weight pass from smem: thread t accumulates column t ---
        const float* xp = sx + tid;
        int r = 0;
        #pragma unroll
        for (; r + 4 <= cl; r += 4) {
            float w0 = sg[r + 0], w1 = sg[r + 1], w2 = sg[r + 2], w3 = sg[r + 3];
            float v0 = xp[(r + 0) * DNUM];
            float v1 = xp[(r + 1) * DNUM];
            float v2 = xp[(r + 2) * DNUM];
            float v3 = xp[(r + 3) * DNUM];
            d_run += w0 + w1 + w2 + w3;
            acc = fmaf(w0, v0, acc);
            acc = fmaf(w1, v1, acc);
            acc = fmaf(w2, v2, acc);
            acc = fmaf(w3, v3, acc);
        }
        for (; r < cl; r++) {
            float w = sg[r];
            d_run += w;
            acc = fmaf(w, xp[r * DNUM], acc);
        }

        m_run = m_new;
        __syncthreads();   // protect sx/sg before next tile overwrites
    }

    out[(size_t)g * DNUM + tid] = (e > s) ? (acc / d_run) : 0.0f;
}

// ---------------------------------------------------------------------------
extern "C" void kernel_launch(void* const* d_in, const int* in_sizes, int n_in,
                              void* d_out, int out_size) {
    const float* x     = (const float*)d_in[0];
    const void*  batch = d_in[1];
    const float* Wg    = (const float*)d_in[2];
    const float* bg    = (const float*)d_in[3];
    float*       out   = (float*)d_out;
    const int n = in_sizes[1];

    detect_kernel<<<1, 1>>>(batch, n);
    seg_offsets_kernel<<<(GNUM + 1 + 255) / 256, 256>>>(batch, n);
    pool_kernel<<<GNUM, 256>>>(x, Wg, bg, out);
}

// round 5
// speedup vs baseline: 2.3943x; 1.3103x over previous
#include <cuda_runtime.h>
#include <cuda_bf16.h>
#include <math.h>

#define DNUM 256
#define GNUM 4096
#define TR   16           // tile rows per buffer (16 KB); double-buffered
#define NEG_BIG (-1e30f)

// Device-global scratch (no allocations allowed)
__device__ int g_seg_start[GNUM + 1];

// ---------------------------------------------------------------------------
// cp.async helpers
// ---------------------------------------------------------------------------
__device__ __forceinline__ void cp_async16(unsigned smem_addr, const void* gptr) {
    asm volatile("cp.async.cg.shared.global [%0], [%1], 16;\n"
                 :: "r"(smem_addr), "l"(gptr));
}
__device__ __forceinline__ void cp_commit() {
    asm volatile("cp.async.commit_group;\n");
}
template <int N>
__device__ __forceinline__ void cp_wait() {
    asm volatile("cp.async.wait_group %0;\n" :: "n"(N));
}

// ---------------------------------------------------------------------------
// Segment offsets via binary search over the sorted batch array.
// int64/int32 width detected locally per thread (batch values < 4096, so
// int64 LE mid-array word pairs look like (nonzero, 0)). Deterministic.
// ---------------------------------------------------------------------------
__global__ void seg_offsets_kernel(const void* __restrict__ batch, int n) {
    int t = blockIdx.x * blockDim.x + threadIdx.x;
    if (t > GNUM) return;

    const int* p = (const int*)batch;
    long base = ((long)(n / 2)) & ~1L;
    int hits = 0;
    #pragma unroll
    for (int k = 0; k < 16; k += 2) {
        if (p[base + k + 1] == 0 && p[base + k] != 0) hits++;
    }
    const int is64 = (hits >= 6) ? 1 : 0;

    if (t == GNUM) { g_seg_start[GNUM] = n; return; }
    int lo = 0, hi = n;
    while (lo < hi) {
        int mid = (lo + hi) >> 1;
        long long v = is64 ? ((const long long*)batch)[mid]
                           : (long long)p[mid];
        if (v < (long long)t) lo = mid + 1; else hi = mid;
    }
    g_seg_start[t] = lo;
}

// ---------------------------------------------------------------------------
// One block per segment, 256 threads (thread t owns output column t).
// Single DRAM read of x via cp.async double-buffered smem staging.
// Online softmax across TR-row tiles; warp 0 does the scalar bookkeeping.
// ---------------------------------------------------------------------------
__global__ __launch_bounds__(256)
void pool_kernel(const float* __restrict__ x,
                 const float* __restrict__ Wg,
                 const float* __restrict__ bg,
                 float* __restrict__ out) {
    __shared__ float sx[2][TR * DNUM];   // 2 x 16 KB tiles
    __shared__ float sg[TR];             // raw gates
    __shared__ float sw[TR];             // exp weights
    __shared__ float s_scale;
    __shared__ float s_wsum;

    const int g    = blockIdx.x;
    const int s    = g_seg_start[g];
    const int e    = g_seg_start[g + 1];
    const int tid  = threadIdx.x;
    const int lane = tid & 31;
    const int wid  = tid >> 5;

    // Wg hoisted into registers for the gate pass (lane-strided)
    float wreg[8];
    #pragma unroll
    for (int j = 0; j < 8; j++) wreg[j] = Wg[lane + 32 * j];
    const float b0 = bg[0];

    float acc   = 0.0f;
    float d_run = 0.0f;
    float m_run = NEG_BIG;   // live only in warp 0's registers (uniform there)

    const float4* __restrict__ x4 = (const float4*)x;
    const unsigned sbase0 = (unsigned)__cvta_generic_to_shared(&sx[0][0]);
    const unsigned sbase1 = (unsigned)__cvta_generic_to_shared(&sx[1][0]);

    // --- prefetch tile 0 ---
    if (s < e) {
        const int cl0 = min(TR, e - s);
        const int nw  = cl0 * (DNUM / 4);
        const float4* src = x4 + (size_t)s * (DNUM / 4);
        #pragma unroll
        for (int i = tid; i < nw; i += 256)
            cp_async16(sbase0 + (unsigned)i * 16u, src + i);
        cp_commit();
    }

    int buf = 0;
    for (int c0 = s; c0 < e; c0 += TR) {
        const int cl = min(TR, e - c0);

        // --- issue prefetch of next tile into the other buffer, then wait ---
        const int c1 = c0 + TR;
        if (c1 < e) {
            const int cln = min(TR, e - c1);
            const int nw  = cln * (DNUM / 4);
            const unsigned dst = buf ? sbase0 : sbase1;
            const float4* src = x4 + (size_t)c1 * (DNUM / 4);
            #pragma unroll
            for (int i = tid; i < nw; i += 256)
                cp_async16(dst + (unsigned)i * 16u, src + i);
            cp_commit();
            cp_wait<1>();      // current tile's group has landed
        } else {
            cp_wait<0>();
        }
        __syncthreads();       // (a) tile `buf` visible to all

        // --- gate pass from smem: one warp per row ---
        const float* xt = sx[buf];
        for (int r = wid; r < cl; r += 8) {
            const float* xr = xt + r * DNUM;
            float sum = 0.0f;
            #pragma unroll
            for (int j = 0; j < 8; j++) sum = fmaf(xr[lane + 32 * j], wreg[j], sum);
            #pragma unroll
            for (int o = 16; o > 0; o >>= 1)
                sum += __shfl_down_sync(0xFFFFFFFFu, sum, o);
            if (lane == 0) sg[r] = sum + b0;
        }
        __syncthreads();       // (b) gates ready

        // --- warp 0: tile max, online rescale factors, exp weights ---
        if (wid == 0) {
            float gv = (lane < cl) ? sg[lane] : NEG_BIG;
            float mc = gv;
            #pragma unroll
            for (int o = 16; o > 0; o >>= 1)
                mc = fmaxf(mc, __shfl_xor_sync(0xFFFFFFFFu, mc, o));
            const float m_new = fmaxf(m_run, mc);
            const float scale = __expf(m_run - m_new);
            const float w = (lane < cl) ? __expf(gv - m_new) : 0.0f;
            if (lane < TR) sw[lane] = w;
            float wsum = w;
            #pragma unroll
            for (int o = 16; o > 0; o >>= 1)
                wsum += __shfl_xor_sync(0xFFFFFFFFu, wsum, o);
            if (lane == 0) { s_scale = scale; s_wsum = wsum; }
            m_run = m_new;
        }
        __syncthreads();       // (c) weights/scale ready

        // --- weight pass: thread t accumulates column t ---
        const float scale = s_scale;
        acc   *= scale;
        d_run  = d_run * scale + s_wsum;

        const float* xp = xt + tid;
        int r = 0;
        #pragma unroll
        for (; r + 4 <= cl; r += 4) {
            float w0 = sw[r + 0], w1 = sw[r + 1], w2 = sw[r + 2], w3 = sw[r + 3];
            float v0 = xp[(r + 0) * DNUM];
            float v1 = xp[(r + 1) * DNUM];
            float v2 = xp[(r + 2) * DNUM];
            float v3 = xp[(r + 3) * DNUM];
            acc = fmaf(w0, v0, acc);
            acc = fmaf(w1, v1, acc);
            acc = fmaf(w2, v2, acc);
            acc = fmaf(w3, v3, acc);
        }
        for (; r < cl; r++)
            acc = fmaf(sw[r], xp[r * DNUM], acc);

        __syncthreads();       // (d) all done with `buf` before it is re-prefetched
        buf ^= 1;
    }

    out[(size_t)g * DNUM + tid] = (e > s) ? (acc / d_run) : 0.0f;
}

// ---------------------------------------------------------------------------
extern "C" void kernel_launch(void* const* d_in, const int* in_sizes, int n_in,
                              void* d_out, int out_size) {
    const float* x     = (const float*)d_in[0];
    const void*  batch = d_in[1];
    const float* Wg    = (const float*)d_in[2];
    const float* bg    = (const float*)d_in[3];
    float*       out   = (float*)d_out;
    const int n = in_sizes[1];

    seg_offsets_kernel<<<(GNUM + 1 + 255) / 256, 256>>>(batch, n);
    pool_kernel<<<GNUM, 256>>>(x, Wg, bg, out);
}